// round 1
// baseline (speedup 1.0000x reference)
#include <cuda_runtime.h>
#include <math.h>

#define BATCH 4
#define SEQ   2048
#define DIM   1024
#define MTOT  (BATCH*SEQ)

// Scratch (allocation-free rule: __device__ globals)
__device__ float g_Q[(size_t)BATCH*SEQ*DIM];   // 32 MB
__device__ float g_K[(size_t)BATCH*SEQ*DIM];   // 32 MB
__device__ float g_V[(size_t)BATCH*SEQ*DIM];   // 32 MB
__device__ float g_P[(size_t)BATCH*SEQ*SEQ];   // 64 MB

// ---------------------------------------------------------------------------
// GEMM-NT: C[m,n] = scale * sum_k A[m,k]*B[n,k] (+ bias[n])
// Both A and B are K-contiguous (lda/ldb = elements per row).
// Tile 128x128, BK=16, 256 threads, 8x8 per thread.
// causal: skip blocks with bx > by (entire block is above the diagonal).
// ---------------------------------------------------------------------------
__global__ __launch_bounds__(256, 2)
void gemm_nt(const float* __restrict__ A, const float* __restrict__ B,
             const float* __restrict__ bias, float* __restrict__ C,
             int K, int lda, int ldb, int ldc,
             long sA, long sB, long sC, float scale, int causal)
{
    const int bx = blockIdx.x, by = blockIdx.y, bz = blockIdx.z;
    if (causal && bx > by) return;
    A += (size_t)bz * sA; B += (size_t)bz * sB; C += (size_t)bz * sC;

    __shared__ float As[16][132];
    __shared__ float Bs[16][132];

    const int tid  = threadIdx.x;
    const int arow = tid >> 2;          // 0..63
    const int ak4  = (tid & 3) << 2;    // 0,4,8,12
    const int tx   = tid & 15;
    const int ty   = tid >> 4;

    const float* Ab = A + (size_t)(by * 128) * lda;
    const float* Bb = B + (size_t)(bx * 128) * ldb;

    float acc[8][8];
    #pragma unroll
    for (int i = 0; i < 8; i++)
        #pragma unroll
        for (int j = 0; j < 8; j++) acc[i][j] = 0.f;

    for (int k0 = 0; k0 < K; k0 += 16) {
        #pragma unroll
        for (int i = 0; i < 2; i++) {
            int r = arow + i * 64;
            float4 va = *(const float4*)(Ab + (size_t)r * lda + k0 + ak4);
            As[ak4+0][r] = va.x; As[ak4+1][r] = va.y;
            As[ak4+2][r] = va.z; As[ak4+3][r] = va.w;
            float4 vb = *(const float4*)(Bb + (size_t)r * ldb + k0 + ak4);
            Bs[ak4+0][r] = vb.x; Bs[ak4+1][r] = vb.y;
            Bs[ak4+2][r] = vb.z; Bs[ak4+3][r] = vb.w;
        }
        __syncthreads();
        #pragma unroll
        for (int k = 0; k < 16; k++) {
            float a[8], b[8];
            *(float4*)(a)     = *(const float4*)&As[k][ty*8];
            *(float4*)(a + 4) = *(const float4*)&As[k][ty*8 + 4];
            *(float4*)(b)     = *(const float4*)&Bs[k][tx*8];
            *(float4*)(b + 4) = *(const float4*)&Bs[k][tx*8 + 4];
            #pragma unroll
            for (int i = 0; i < 8; i++)
                #pragma unroll
                for (int j = 0; j < 8; j++)
                    acc[i][j] = fmaf(a[i], b[j], acc[i][j]);
        }
        __syncthreads();
    }

    #pragma unroll
    for (int i = 0; i < 8; i++) {
        int m = by * 128 + ty * 8 + i;
        #pragma unroll
        for (int j = 0; j < 8; j += 4) {
            int n = bx * 128 + tx * 8 + j;
            float4 v;
            v.x = acc[i][j+0] * scale;
            v.y = acc[i][j+1] * scale;
            v.z = acc[i][j+2] * scale;
            v.w = acc[i][j+3] * scale;
            if (bias) {
                v.x += bias[n+0]; v.y += bias[n+1];
                v.z += bias[n+2]; v.w += bias[n+3];
            }
            *(float4*)(C + (size_t)m * ldc + n) = v;
        }
    }
}

// ---------------------------------------------------------------------------
// GEMM-NN: C[m,n] = sum_k A[m,k]*B[k,n].  A is K-contiguous, B is N-contiguous.
// causal: K-loop truncated to (by+1)*128 (P is zero above that for rows in by).
// ---------------------------------------------------------------------------
__global__ __launch_bounds__(256, 2)
void gemm_nn(const float* __restrict__ A, const float* __restrict__ B,
             float* __restrict__ C,
             int K, int lda, int ldb, int ldc,
             long sA, long sB, long sC, int causal)
{
    const int bx = blockIdx.x, by = blockIdx.y, bz = blockIdx.z;
    A += (size_t)bz * sA; B += (size_t)bz * sB; C += (size_t)bz * sC;

    __shared__ float As[16][132];
    __shared__ float Bs[16][132];

    const int tid  = threadIdx.x;
    const int arow = tid >> 2;
    const int ak4  = (tid & 3) << 2;
    const int brow = tid >> 5;          // 0..7
    const int bcol = (tid & 31) << 2;   // 0..124
    const int tx   = tid & 15;
    const int ty   = tid >> 4;

    const float* Ab = A + (size_t)(by * 128) * lda;

    int Keff = causal ? min(K, (by + 1) * 128) : K;

    float acc[8][8];
    #pragma unroll
    for (int i = 0; i < 8; i++)
        #pragma unroll
        for (int j = 0; j < 8; j++) acc[i][j] = 0.f;

    for (int k0 = 0; k0 < Keff; k0 += 16) {
        #pragma unroll
        for (int i = 0; i < 2; i++) {
            int r = arow + i * 64;
            float4 va = *(const float4*)(Ab + (size_t)r * lda + k0 + ak4);
            As[ak4+0][r] = va.x; As[ak4+1][r] = va.y;
            As[ak4+2][r] = va.z; As[ak4+3][r] = va.w;
            int rb = brow + i * 8;
            float4 vb = *(const float4*)(B + (size_t)(k0 + rb) * ldb + bx * 128 + bcol);
            *(float4*)&Bs[rb][bcol] = vb;
        }
        __syncthreads();
        #pragma unroll
        for (int k = 0; k < 16; k++) {
            float a[8], b[8];
            *(float4*)(a)     = *(const float4*)&As[k][ty*8];
            *(float4*)(a + 4) = *(const float4*)&As[k][ty*8 + 4];
            *(float4*)(b)     = *(const float4*)&Bs[k][tx*8];
            *(float4*)(b + 4) = *(const float4*)&Bs[k][tx*8 + 4];
            #pragma unroll
            for (int i = 0; i < 8; i++)
                #pragma unroll
                for (int j = 0; j < 8; j++)
                    acc[i][j] = fmaf(a[i], b[j], acc[i][j]);
        }
        __syncthreads();
    }

    #pragma unroll
    for (int i = 0; i < 8; i++) {
        int m = by * 128 + ty * 8 + i;
        #pragma unroll
        for (int j = 0; j < 8; j += 4) {
            int n = bx * 128 + tx * 8 + j;
            *(float4*)(C + (size_t)m * ldc + n) =
                make_float4(acc[i][j+0], acc[i][j+1], acc[i][j+2], acc[i][j+3]);
        }
    }
}

// ---------------------------------------------------------------------------
// Causal row softmax over P (in place). One CTA per (b, q) row.
// Reads k in [0, q], writes normalized probs there and zeros in (q, SEQ).
// ---------------------------------------------------------------------------
__global__ __launch_bounds__(256)
void softmax_causal(float* __restrict__ P)
{
    const int row = blockIdx.x;          // b*SEQ + q ; P row stride = SEQ
    const int q   = row & (SEQ - 1);
    float* p = P + (size_t)row * SEQ;
    const int n = q + 1;
    const int tid = threadIdx.x;
    __shared__ float red[8];

    float m = -1e30f;
    for (int i = tid; i < n; i += 256) m = fmaxf(m, p[i]);
    #pragma unroll
    for (int o = 16; o; o >>= 1) m = fmaxf(m, __shfl_xor_sync(0xffffffffu, m, o));
    if ((tid & 31) == 0) red[tid >> 5] = m;
    __syncthreads();
    if (tid == 0) {
        float mm = red[0];
        #pragma unroll
        for (int i = 1; i < 8; i++) mm = fmaxf(mm, red[i]);
        red[0] = mm;
    }
    __syncthreads();
    m = red[0];
    __syncthreads();

    float s = 0.f;
    for (int i = tid; i < n; i += 256) s += expf(p[i] - m);
    #pragma unroll
    for (int o = 16; o; o >>= 1) s += __shfl_xor_sync(0xffffffffu, s, o);
    if ((tid & 31) == 0) red[tid >> 5] = s;
    __syncthreads();
    if (tid == 0) {
        float ss = 0.f;
        #pragma unroll
        for (int i = 0; i < 8; i++) ss += red[i];
        red[0] = ss;
    }
    __syncthreads();
    const float inv = 1.0f / red[0];

    for (int i = tid; i < n; i += 256) p[i] = expf(p[i] - m) * inv;
    for (int i = n + tid; i < SEQ; i += 256) p[i] = 0.f;
}

// ---------------------------------------------------------------------------
extern "C" void kernel_launch(void* const* d_in, const int* in_sizes, int n_in,
                              void* d_out, int out_size)
{
    const float* x  = (const float*)d_in[0];
    const float* Wq = (const float*)d_in[1];
    const float* bq = (const float*)d_in[2];
    const float* Wk = (const float*)d_in[3];
    const float* bk = (const float*)d_in[4];
    const float* Wv = (const float*)d_in[5];
    const float* bv = (const float*)d_in[6];
    float* out = (float*)d_out;

    float *Q, *Kb, *V, *P;
    cudaGetSymbolAddress((void**)&Q,  g_Q);
    cudaGetSymbolAddress((void**)&Kb, g_K);
    cudaGetSymbolAddress((void**)&V,  g_V);
    cudaGetSymbolAddress((void**)&P,  g_P);

    const float SCALE = 0.03125f;  // 1/sqrt(1024)

    dim3 t(256);

    // QKV projections: [8192,1024] = x[8192,1024] @ W^T + b
    dim3 gq(DIM / 128, MTOT / 128, 1);
    gemm_nt<<<gq, t>>>(x, Wq, bq, Q,  DIM, DIM, DIM, DIM, 0, 0, 0, 1.0f, 0);
    gemm_nt<<<gq, t>>>(x, Wk, bk, Kb, DIM, DIM, DIM, DIM, 0, 0, 0, 1.0f, 0);
    gemm_nt<<<gq, t>>>(x, Wv, bv, V,  DIM, DIM, DIM, DIM, 0, 0, 0, 1.0f, 0);

    // scores = Q @ K^T * SCALE, lower-triangle blocks only, batched over z
    dim3 gs(SEQ / 128, SEQ / 128, BATCH);
    gemm_nt<<<gs, t>>>(Q, Kb, nullptr, P, DIM, DIM, DIM, SEQ,
                       (long)SEQ * DIM, (long)SEQ * DIM, (long)SEQ * SEQ,
                       SCALE, 1);

    // causal softmax (in place on P), zeros above diagonal
    softmax_causal<<<MTOT, 256>>>(P);

    // out = P @ V, K-loop truncated at causal boundary
    dim3 go(DIM / 128, SEQ / 128, BATCH);
    gemm_nn<<<go, t>>>(P, V, out, SEQ, SEQ, DIM, DIM,
                       (long)SEQ * SEQ, (long)SEQ * DIM, (long)SEQ * DIM, 1);
}

// round 4
// speedup vs baseline: 3.5425x; 3.5425x over previous
#include <cuda_runtime.h>
#include <cstdint>
#include <math.h>

#define BATCH 4
#define SEQ   2048
#define DIM   1024
#define MTOT  (BATCH*SEQ)

// Scratch (__device__ globals; allocation-free rule)
__device__ float g_Q [(size_t)BATCH*SEQ*DIM];   // 32 MB
__device__ float g_K [(size_t)BATCH*SEQ*DIM];   // 32 MB
__device__ float g_V [(size_t)BATCH*SEQ*DIM];   // 32 MB
__device__ float g_VT[(size_t)BATCH*SEQ*DIM];   // 32 MB (V transposed: [D][S])
__device__ float g_P [(size_t)BATCH*SEQ*SEQ];   // 64 MB

// ---------------------------------------------------------------------------
__device__ __forceinline__ uint32_t smem_u32(const void* p){
    uint32_t a;
    asm("{ .reg .u64 t; cvta.to.shared.u64 t, %1; cvt.u32.u64 %0, t; }"
        : "=r"(a) : "l"(p));
    return a;
}
#define SW128(o) ((o) ^ (((o) >> 3) & 0x70))

__device__ __forceinline__ void cp16(uint32_t s, const void* g){
    asm volatile("cp.async.cg.shared.global [%0], [%1], 16;" :: "r"(s), "l"(g));
}
__device__ __forceinline__ void tf32ip(uint32_t& u){
    asm("cvt.rna.tf32.f32 %0, %1;" : "=r"(u) : "f"(__uint_as_float(u)));
}

// ---------------------------------------------------------------------------
// tf32 HMMA GEMM-NT: C[m,n] = scale * sum_k A[m,k]*B[n,k] (+ bias[n])
// CTA tile 128x128, BK=32 double-buffered cp.async, 8 warps of 32x64.
// mode: 0 plain; 1 skip blocks bx>by (causal scores); 2 truncate K at
//       (by+1)*128 (P*V, P zero above diagonal).
// ---------------------------------------------------------------------------
__global__ __launch_bounds__(256, 2)
void gemm_mma(const float* __restrict__ A, const float* __restrict__ B,
              const float* __restrict__ bias, float* __restrict__ C,
              int K, int lda, int ldb, int ldc,
              long sA, long sB, long sC, float scale, int mode)
{
    const int bx = blockIdx.x, by = blockIdx.y, bz = blockIdx.z;
    if (mode == 1 && bx > by) return;
    A += (size_t)bz * sA; B += (size_t)bz * sB; C += (size_t)bz * sC;

    const int Keff = (mode == 2) ? min(K, (by + 1) * 128) : K;
    const int nch  = Keff >> 5;

    extern __shared__ char dsm[];
    const uint32_t base = (smem_u32(dsm) + 1023) & ~1023u;
    const int tid = threadIdx.x, lane = tid & 31, wid = tid >> 5;
    const int wm = wid & 3, wn = wid >> 2;     // warp grid 4 (M) x 2 (N)

    const float* Ab = A + (size_t)(by * 128) * lda;
    const float* Bb = B + (size_t)(bx * 128) * ldb;

    // tile: 128 rows x 32 f32 (128B rows), SW128 swizzle, 16KB
    auto load_tile = [&](const float* gb, int ld, int k0, uint32_t sbase){
        #pragma unroll
        for (int it = 0; it < 4; it++){
            int idx = tid + it * 256;
            int r = idx >> 3, c4 = idx & 7;
            uint32_t off = (uint32_t)(r * 128 + c4 * 16);
            cp16(sbase + SW128(off), gb + (size_t)r * ld + k0 + c4 * 4);
        }
    };

    // per-lane ldmatrix offsets (tile-relative, pre-swizzle)
    // A x4: m0..m3 = quadrants (rows0-7/k0-3),(rows8-15/k0-3),(rows0-7/k4-7),(rows8-15/k4-7)
    const uint32_t offA = (uint32_t)((wm*32 + (lane & 15)) * 128 + (lane >> 4) * 16);
    // B x4 over n-tile pair {2g,2g+1}: (n0-7/k0-3),(n0-7/k4-7),(n8-15/k0-3),(n8-15/k4-7)
    uint32_t offB[4];
    #pragma unroll
    for (int g = 0; g < 4; g++)
        offB[g] = (uint32_t)((wn*64 + g*16 + (lane & 7) + ((lane >> 4) & 1) * 8) * 128
                             + ((lane >> 3) & 1) * 16);

    float acc[2][8][4];
    #pragma unroll
    for (int mt = 0; mt < 2; mt++)
        #pragma unroll
        for (int nt = 0; nt < 8; nt++)
            #pragma unroll
            for (int j = 0; j < 4; j++) acc[mt][nt][j] = 0.f;

    // prologue: chunks 0,1
    load_tile(Ab, lda, 0, base);
    load_tile(Bb, ldb, 0, base + 16384);
    asm volatile("cp.async.commit_group;");
    if (nch > 1){
        load_tile(Ab, lda, 32, base + 32768);
        load_tile(Bb, ldb, 32, base + 49152);
    }
    asm volatile("cp.async.commit_group;");

    for (int i = 0; i < nch; i++){
        const uint32_t ab = base + (uint32_t)(i & 1) * 32768;
        const uint32_t bb = ab + 16384;
        asm volatile("cp.async.wait_group 1;");
        __syncthreads();

        #pragma unroll
        for (int ks = 0; ks < 4; ks++){
            const uint32_t kadd = ks * 32;
            uint32_t ar[2][4];
            #pragma unroll
            for (int mt = 0; mt < 2; mt++){
                uint32_t ad = ab + SW128(offA + (uint32_t)mt * 2048 + kadd);
                asm volatile(
                    "ldmatrix.sync.aligned.m8n8.x4.shared.b16 {%0,%1,%2,%3}, [%4];"
                    : "=r"(ar[mt][0]), "=r"(ar[mt][1]),
                      "=r"(ar[mt][2]), "=r"(ar[mt][3]) : "r"(ad));
            }
            uint32_t br[8][2];
            #pragma unroll
            for (int g = 0; g < 4; g++){
                uint32_t ad = bb + SW128(offB[g] + kadd);
                asm volatile(
                    "ldmatrix.sync.aligned.m8n8.x4.shared.b16 {%0,%1,%2,%3}, [%4];"
                    : "=r"(br[2*g][0]), "=r"(br[2*g][1]),
                      "=r"(br[2*g+1][0]), "=r"(br[2*g+1][1]) : "r"(ad));
            }
            #pragma unroll
            for (int mt = 0; mt < 2; mt++)
                #pragma unroll
                for (int j = 0; j < 4; j++) tf32ip(ar[mt][j]);
            #pragma unroll
            for (int nt = 0; nt < 8; nt++){
                tf32ip(br[nt][0]); tf32ip(br[nt][1]);
            }
            #pragma unroll
            for (int mt = 0; mt < 2; mt++)
                #pragma unroll
                for (int nt = 0; nt < 8; nt++){
                    asm volatile(
                        "mma.sync.aligned.m16n8k8.row.col.f32.tf32.tf32.f32 "
                        "{%0,%1,%2,%3}, {%4,%5,%6,%7}, {%8,%9}, {%0,%1,%2,%3};"
                        : "+f"(acc[mt][nt][0]), "+f"(acc[mt][nt][1]),
                          "+f"(acc[mt][nt][2]), "+f"(acc[mt][nt][3])
                        : "r"(ar[mt][0]), "r"(ar[mt][1]),
                          "r"(ar[mt][2]), "r"(ar[mt][3]),
                          "r"(br[nt][0]), "r"(br[nt][1]));
                }
        }
        __syncthreads();
        if (i + 2 < nch){
            load_tile(Ab, lda, (i + 2) * 32, ab);
            load_tile(Bb, ldb, (i + 2) * 32, bb);
        }
        asm volatile("cp.async.commit_group;");  // keep group counts uniform
    }

    // epilogue: fragment layout c0,c1 @ (r, 2c),(r,2c+1); c2,c3 @ (r+8, ...)
    const int r0 = lane >> 2, c0 = (lane & 3) * 2;
    #pragma unroll
    for (int mt = 0; mt < 2; mt++){
        const int mrow = by * 128 + wm * 32 + mt * 16 + r0;
        #pragma unroll
        for (int nt = 0; nt < 8; nt++){
            const int col = bx * 128 + wn * 64 + nt * 8 + c0;
            float2 v0, v1;
            v0.x = acc[mt][nt][0] * scale; v0.y = acc[mt][nt][1] * scale;
            v1.x = acc[mt][nt][2] * scale; v1.y = acc[mt][nt][3] * scale;
            if (bias){
                float b0 = bias[col], b1 = bias[col + 1];
                v0.x += b0; v0.y += b1; v1.x += b0; v1.y += b1;
            }
            *(float2*)(C + (size_t)mrow * ldc + col)       = v0;
            *(float2*)(C + (size_t)(mrow + 8) * ldc + col) = v1;
        }
    }
}

// ---------------------------------------------------------------------------
// V transpose: VT[b][d][s] = V[b][s][d]
// ---------------------------------------------------------------------------
__global__ __launch_bounds__(256)
void transpose_sd(const float* __restrict__ V, float* __restrict__ VT)
{
    __shared__ float t[32][33];
    const int b  = blockIdx.z;
    const int s0 = blockIdx.x * 32, d0 = blockIdx.y * 32;
    const float* Vb = V  + (size_t)b * SEQ * DIM;
    float* VTb      = VT + (size_t)b * SEQ * DIM;
    const int x = threadIdx.x, y = threadIdx.y;   // 32 x 8
    #pragma unroll
    for (int i = 0; i < 32; i += 8)
        t[y + i][x] = Vb[(size_t)(s0 + y + i) * DIM + d0 + x];
    __syncthreads();
    #pragma unroll
    for (int i = 0; i < 32; i += 8)
        VTb[(size_t)(d0 + y + i) * SEQ + s0 + x] = t[x][y + i];
}

// ---------------------------------------------------------------------------
// Causal row softmax over P (in place), zeros above diagonal.
// ---------------------------------------------------------------------------
__global__ __launch_bounds__(256)
void softmax_causal(float* __restrict__ P)
{
    const int row = blockIdx.x;
    const int q   = row & (SEQ - 1);
    float* p = P + (size_t)row * SEQ;
    const int n = q + 1;
    const int tid = threadIdx.x;
    __shared__ float red[8];

    float m = -1e30f;
    for (int i = tid; i < n; i += 256) m = fmaxf(m, p[i]);
    #pragma unroll
    for (int o = 16; o; o >>= 1) m = fmaxf(m, __shfl_xor_sync(0xffffffffu, m, o));
    if ((tid & 31) == 0) red[tid >> 5] = m;
    __syncthreads();
    if (tid == 0){
        float mm = red[0];
        #pragma unroll
        for (int i = 1; i < 8; i++) mm = fmaxf(mm, red[i]);
        red[0] = mm;
    }
    __syncthreads();
    m = red[0];
    __syncthreads();

    float s = 0.f;
    for (int i = tid; i < n; i += 256) s += expf(p[i] - m);
    #pragma unroll
    for (int o = 16; o; o >>= 1) s += __shfl_xor_sync(0xffffffffu, s, o);
    if ((tid & 31) == 0) red[tid >> 5] = s;
    __syncthreads();
    if (tid == 0){
        float ss = 0.f;
        #pragma unroll
        for (int i = 0; i < 8; i++) ss += red[i];
        red[0] = ss;
    }
    __syncthreads();
    const float inv = 1.0f / red[0];

    for (int i = tid; i < n; i += 256) p[i] = expf(p[i] - m) * inv;
    for (int i = n + tid; i < SEQ; i += 256) p[i] = 0.f;
}

// ---------------------------------------------------------------------------
extern "C" void kernel_launch(void* const* d_in, const int* in_sizes, int n_in,
                              void* d_out, int out_size)
{
    const float* x  = (const float*)d_in[0];
    const float* Wq = (const float*)d_in[1];
    const float* bq = (const float*)d_in[2];
    const float* Wk = (const float*)d_in[3];
    const float* bk = (const float*)d_in[4];
    const float* Wv = (const float*)d_in[5];
    const float* bv = (const float*)d_in[6];
    float* out = (float*)d_out;

    float *Q, *Kb, *V, *VT, *P;
    cudaGetSymbolAddress((void**)&Q,  g_Q);
    cudaGetSymbolAddress((void**)&Kb, g_K);
    cudaGetSymbolAddress((void**)&V,  g_V);
    cudaGetSymbolAddress((void**)&VT, g_VT);
    cudaGetSymbolAddress((void**)&P,  g_P);

    const size_t SHM = 66560;  // 64KB tiles + alignment slack
    static bool attr_set = false;
    if (!attr_set){
        cudaFuncSetAttribute(gemm_mma, cudaFuncAttributeMaxDynamicSharedMemorySize, (int)SHM);
        attr_set = true;
    }

    const long SD = (long)SEQ * DIM;
    const long SS = (long)SEQ * SEQ;
    dim3 t(256);

    // QKV projections: [8192,1024] = x @ W^T + b
    dim3 gq(DIM / 128, MTOT / 128, 1);
    gemm_mma<<<gq, t, SHM>>>(x, Wq, bq, Q,  DIM, DIM, DIM, DIM, 0, 0, 0, 1.0f, 0);
    gemm_mma<<<gq, t, SHM>>>(x, Wk, bk, Kb, DIM, DIM, DIM, DIM, 0, 0, 0, 1.0f, 0);
    gemm_mma<<<gq, t, SHM>>>(x, Wv, bv, V,  DIM, DIM, DIM, DIM, 0, 0, 0, 1.0f, 0);

    // VT[b][d][s] = V[b][s][d]
    transpose_sd<<<dim3(SEQ/32, DIM/32, BATCH), dim3(32, 8)>>>(V, VT);

    // scores = Q @ K^T * (1/32), lower-triangle blocks only
    dim3 gs(SEQ / 128, SEQ / 128, BATCH);
    gemm_mma<<<gs, t, SHM>>>(Q, Kb, nullptr, P, DIM, DIM, DIM, SEQ,
                             SD, SD, SS, 0.03125f, 1);

    // causal softmax in place (zeros above diagonal)
    softmax_causal<<<MTOT, 256>>>(P);

    // out = P @ V  (= P @ VT^T as NT), K truncated at causal boundary
    dim3 go(DIM / 128, SEQ / 128, BATCH);
    gemm_mma<<<go, t, SHM>>>(P, VT, nullptr, out, SEQ, SEQ, SEQ, DIM,
                             SS, SD, SD, 1.0f, 2);
}

// round 5
// speedup vs baseline: 4.1523x; 1.1721x over previous
#include <cuda_runtime.h>
#include <cstdint>
#include <math.h>

#define BATCH 4
#define SEQ   2048
#define DIM   1024
#define MTOT  (BATCH*SEQ)

// Scratch (__device__ globals; allocation-free rule)
__device__ float g_Q [(size_t)BATCH*SEQ*DIM];   // 32 MB
__device__ float g_K [(size_t)BATCH*SEQ*DIM];   // 32 MB
__device__ float g_V [(size_t)BATCH*SEQ*DIM];   // 32 MB
__device__ float g_VT[(size_t)BATCH*SEQ*DIM];   // 32 MB (V^T per batch: [D][S])
__device__ float g_P [(size_t)BATCH*SEQ*SEQ];   // 64 MB
__device__ float g_X [(size_t)MTOT*DIM];        // 32 MB (x rounded to tf32)
__device__ float g_W [(size_t)3*DIM*DIM];       // 12 MB (Wq|Wk|Wv rounded)

// ---------------------------------------------------------------------------
__device__ __forceinline__ uint32_t smem_u32(const void* p){
    uint32_t a;
    asm("{ .reg .u64 t; cvta.to.shared.u64 t, %1; cvt.u32.u64 %0, t; }"
        : "=r"(a) : "l"(p));
    return a;
}
#define SW128(o) ((o) ^ (((o) >> 3) & 0x70))

__device__ __forceinline__ void cp16(uint32_t s, const void* g){
    asm volatile("cp.async.cg.shared.global [%0], [%1], 16;" :: "r"(s), "l"(g));
}
__device__ __forceinline__ float tf32r(float f){
    uint32_t u;
    asm("cvt.rna.tf32.f32 %0, %1;" : "=r"(u) : "f"(f));
    return __uint_as_float(u);
}

// ---------------------------------------------------------------------------
// Elementwise round-to-tf32 (float4 granularity; n % 1024 == 0 here)
// ---------------------------------------------------------------------------
__global__ __launch_bounds__(256)
void round_tf32(const float* __restrict__ src, float* __restrict__ dst, int n4)
{
    int i = blockIdx.x * 256 + threadIdx.x;
    if (i >= n4) return;
    float4 v = ((const float4*)src)[i];
    v.x = tf32r(v.x); v.y = tf32r(v.y); v.z = tf32r(v.z); v.w = tf32r(v.w);
    ((float4*)dst)[i] = v;
}

// ---------------------------------------------------------------------------
// tf32 HMMA GEMM-NT: C[m,n] = scale * sum_k A[m,k]*B[n,k] (+ bias[n])
// ALL operands must already be tf32-rounded (no in-loop cvt).
// CTA tile 128x128, BK=32 double-buffered cp.async, 8 warps of 32x64.
// mode: 0 plain; 1 skip blocks bx>by (causal scores); 2 truncate K at
//       (by+1)*128 (P*V, P zero above diagonal).
// rnd: round outputs to tf32 (for values feeding a later MMA).
// ---------------------------------------------------------------------------
__global__ __launch_bounds__(256, 2)
void gemm_mma(const float* __restrict__ A, const float* __restrict__ B,
              const float* __restrict__ bias, float* __restrict__ C,
              int K, int lda, int ldb, int ldc,
              long sA, long sB, long sC, float scale, int mode, int rnd)
{
    const int bx = blockIdx.x, by = blockIdx.y, bz = blockIdx.z;
    if (mode == 1 && bx > by) return;
    A += (size_t)bz * sA; B += (size_t)bz * sB; C += (size_t)bz * sC;

    const int Keff = (mode == 2) ? min(K, (by + 1) * 128) : K;
    const int nch  = Keff >> 5;

    extern __shared__ char dsm[];
    const uint32_t base = (smem_u32(dsm) + 1023) & ~1023u;
    const int tid = threadIdx.x, lane = tid & 31, wid = tid >> 5;
    const int wm = wid & 3, wn = wid >> 2;     // warp grid 4 (M) x 2 (N)

    const float* Ab = A + (size_t)(by * 128) * lda;
    const float* Bb = B + (size_t)(bx * 128) * ldb;

    // tile: 128 rows x 32 f32 (128B rows), SW128 swizzle, 16KB
    auto load_tile = [&](const float* gb, int ld, int k0, uint32_t sbase){
        #pragma unroll
        for (int it = 0; it < 4; it++){
            int idx = tid + it * 256;
            int r = idx >> 3, c4 = idx & 7;
            uint32_t off = (uint32_t)(r * 128 + c4 * 16);
            cp16(sbase + SW128(off), gb + (size_t)r * ld + k0 + c4 * 4);
        }
    };

    // per-lane ldmatrix offsets (tile-relative, pre-swizzle)
    const uint32_t offA = (uint32_t)((wm*32 + (lane & 15)) * 128 + (lane >> 4) * 16);
    uint32_t offB[4];
    #pragma unroll
    for (int g = 0; g < 4; g++)
        offB[g] = (uint32_t)((wn*64 + g*16 + (lane & 7) + ((lane >> 4) & 1) * 8) * 128
                             + ((lane >> 3) & 1) * 16);

    float acc[2][8][4];
    #pragma unroll
    for (int mt = 0; mt < 2; mt++)
        #pragma unroll
        for (int nt = 0; nt < 8; nt++)
            #pragma unroll
            for (int j = 0; j < 4; j++) acc[mt][nt][j] = 0.f;

    // prologue: chunks 0,1
    load_tile(Ab, lda, 0, base);
    load_tile(Bb, ldb, 0, base + 16384);
    asm volatile("cp.async.commit_group;");
    if (nch > 1){
        load_tile(Ab, lda, 32, base + 32768);
        load_tile(Bb, ldb, 32, base + 49152);
    }
    asm volatile("cp.async.commit_group;");

    for (int i = 0; i < nch; i++){
        const uint32_t ab = base + (uint32_t)(i & 1) * 32768;
        const uint32_t bb = ab + 16384;
        asm volatile("cp.async.wait_group 1;");
        __syncthreads();

        #pragma unroll
        for (int ks = 0; ks < 4; ks++){
            const uint32_t kadd = ks * 32;
            uint32_t ar[2][4];
            #pragma unroll
            for (int mt = 0; mt < 2; mt++){
                uint32_t ad = ab + SW128(offA + (uint32_t)mt * 2048 + kadd);
                asm volatile(
                    "ldmatrix.sync.aligned.m8n8.x4.shared.b16 {%0,%1,%2,%3}, [%4];"
                    : "=r"(ar[mt][0]), "=r"(ar[mt][1]),
                      "=r"(ar[mt][2]), "=r"(ar[mt][3]) : "r"(ad));
            }
            uint32_t br[8][2];
            #pragma unroll
            for (int g = 0; g < 4; g++){
                uint32_t ad = bb + SW128(offB[g] + kadd);
                asm volatile(
                    "ldmatrix.sync.aligned.m8n8.x4.shared.b16 {%0,%1,%2,%3}, [%4];"
                    : "=r"(br[2*g][0]), "=r"(br[2*g][1]),
                      "=r"(br[2*g+1][0]), "=r"(br[2*g+1][1]) : "r"(ad));
            }
            #pragma unroll
            for (int mt = 0; mt < 2; mt++)
                #pragma unroll
                for (int nt = 0; nt < 8; nt++){
                    asm volatile(
                        "mma.sync.aligned.m16n8k8.row.col.f32.tf32.tf32.f32 "
                        "{%0,%1,%2,%3}, {%4,%5,%6,%7}, {%8,%9}, {%0,%1,%2,%3};"
                        : "+f"(acc[mt][nt][0]), "+f"(acc[mt][nt][1]),
                          "+f"(acc[mt][nt][2]), "+f"(acc[mt][nt][3])
                        : "r"(ar[mt][0]), "r"(ar[mt][1]),
                          "r"(ar[mt][2]), "r"(ar[mt][3]),
                          "r"(br[nt][0]), "r"(br[nt][1]));
                }
        }
        __syncthreads();
        if (i + 2 < nch){
            load_tile(Ab, lda, (i + 2) * 32, ab);
            load_tile(Bb, ldb, (i + 2) * 32, bb);
        }
        asm volatile("cp.async.commit_group;");  // keep group counts uniform
    }

    // epilogue
    const int r0 = lane >> 2, c0 = (lane & 3) * 2;
    #pragma unroll
    for (int mt = 0; mt < 2; mt++){
        const int mrow = by * 128 + wm * 32 + mt * 16 + r0;
        #pragma unroll
        for (int nt = 0; nt < 8; nt++){
            const int col = bx * 128 + wn * 64 + nt * 8 + c0;
            float2 v0, v1;
            v0.x = acc[mt][nt][0] * scale; v0.y = acc[mt][nt][1] * scale;
            v1.x = acc[mt][nt][2] * scale; v1.y = acc[mt][nt][3] * scale;
            if (bias){
                float b0 = bias[col], b1 = bias[col + 1];
                v0.x += b0; v0.y += b1; v1.x += b0; v1.y += b1;
            }
            if (rnd){
                v0.x = tf32r(v0.x); v0.y = tf32r(v0.y);
                v1.x = tf32r(v1.x); v1.y = tf32r(v1.y);
            }
            *(float2*)(C + (size_t)mrow * ldc + col)       = v0;
            *(float2*)(C + (size_t)(mrow + 8) * ldc + col) = v1;
        }
    }
}

// ---------------------------------------------------------------------------
// V transpose: VT[b][d][s] = V[b][s][d]   (V already tf32-rounded)
// ---------------------------------------------------------------------------
__global__ __launch_bounds__(256)
void transpose_sd(const float* __restrict__ V, float* __restrict__ VT)
{
    __shared__ float t[32][33];
    const int b  = blockIdx.z;
    const int s0 = blockIdx.x * 32, d0 = blockIdx.y * 32;
    const float* Vb = V  + (size_t)b * SEQ * DIM;
    float* VTb      = VT + (size_t)b * SEQ * DIM;
    const int x = threadIdx.x, y = threadIdx.y;   // 32 x 8
    #pragma unroll
    for (int i = 0; i < 32; i += 8)
        t[y + i][x] = Vb[(size_t)(s0 + y + i) * DIM + d0 + x];
    __syncthreads();
    #pragma unroll
    for (int i = 0; i < 32; i += 8)
        VTb[(size_t)(d0 + y + i) * SEQ + s0 + x] = t[x][y + i];
}

// ---------------------------------------------------------------------------
// Causal row softmax, single pass (row cached in registers), output rounded
// to tf32 (it feeds the P*V MMA). Zeros above the diagonal.
// ---------------------------------------------------------------------------
__global__ __launch_bounds__(256)
void softmax_causal(float* __restrict__ P)
{
    const int row = blockIdx.x;
    const int q   = row & (SEQ - 1);
    float* p = P + (size_t)row * SEQ;
    const int n = q + 1;
    const int tid = threadIdx.x;
    __shared__ float red[8];

    float v[8];
    #pragma unroll
    for (int i = 0; i < 8; i++){
        int idx = tid + i * 256;
        v[i] = (idx < n) ? p[idx] : -INFINITY;
    }

    float m = v[0];
    #pragma unroll
    for (int i = 1; i < 8; i++) m = fmaxf(m, v[i]);
    #pragma unroll
    for (int o = 16; o; o >>= 1) m = fmaxf(m, __shfl_xor_sync(0xffffffffu, m, o));
    if ((tid & 31) == 0) red[tid >> 5] = m;
    __syncthreads();
    if (tid == 0){
        float mm = red[0];
        #pragma unroll
        for (int i = 1; i < 8; i++) mm = fmaxf(mm, red[i]);
        red[0] = mm;
    }
    __syncthreads();
    m = red[0];
    __syncthreads();

    float e[8], s = 0.f;
    #pragma unroll
    for (int i = 0; i < 8; i++){
        e[i] = expf(v[i] - m);        // exp(-inf)=0 for masked lanes
        s += e[i];
    }
    #pragma unroll
    for (int o = 16; o; o >>= 1) s += __shfl_xor_sync(0xffffffffu, s, o);
    if ((tid & 31) == 0) red[tid >> 5] = s;
    __syncthreads();
    if (tid == 0){
        float ss = 0.f;
        #pragma unroll
        for (int i = 0; i < 8; i++) ss += red[i];
        red[0] = ss;
    }
    __syncthreads();
    const float inv = 1.0f / red[0];

    #pragma unroll
    for (int i = 0; i < 8; i++){
        int idx = tid + i * 256;
        if (idx < n) p[idx] = tf32r(e[i] * inv);
    }
    for (int i = n + tid; i < SEQ; i += 256) p[i] = 0.f;
}

// ---------------------------------------------------------------------------
extern "C" void kernel_launch(void* const* d_in, const int* in_sizes, int n_in,
                              void* d_out, int out_size)
{
    const float* x  = (const float*)d_in[0];
    const float* Wq = (const float*)d_in[1];
    const float* bq = (const float*)d_in[2];
    const float* Wk = (const float*)d_in[3];
    const float* bk = (const float*)d_in[4];
    const float* Wv = (const float*)d_in[5];
    const float* bv = (const float*)d_in[6];
    float* out = (float*)d_out;

    float *Q, *Kb, *V, *VT, *P, *X, *W;
    cudaGetSymbolAddress((void**)&Q,  g_Q);
    cudaGetSymbolAddress((void**)&Kb, g_K);
    cudaGetSymbolAddress((void**)&V,  g_V);
    cudaGetSymbolAddress((void**)&VT, g_VT);
    cudaGetSymbolAddress((void**)&P,  g_P);
    cudaGetSymbolAddress((void**)&X,  g_X);
    cudaGetSymbolAddress((void**)&W,  g_W);

    const size_t SHM = 66560;  // 64KB tiles + alignment slack
    static bool attr_set = false;
    if (!attr_set){
        cudaFuncSetAttribute(gemm_mma, cudaFuncAttributeMaxDynamicSharedMemorySize, (int)SHM);
        attr_set = true;
    }

    const long SD = (long)SEQ * DIM;
    const long SS = (long)SEQ * SEQ;
    const int  DD = DIM * DIM;
    dim3 t(256);

    // Pre-round MMA inputs to tf32 (makes in-loop cvt unnecessary, bit-identical)
    round_tf32<<<(MTOT*DIM/4 + 255)/256, 256>>>(x,  X,          MTOT*DIM/4);
    round_tf32<<<(DD/4 + 255)/256, 256>>>(Wq, W,              DD/4);
    round_tf32<<<(DD/4 + 255)/256, 256>>>(Wk, W + DD,         DD/4);
    round_tf32<<<(DD/4 + 255)/256, 256>>>(Wv, W + 2*DD,       DD/4);

    // QKV projections: [8192,1024] = X @ W^T + b ; outputs rounded (feed MMAs)
    dim3 gq(DIM / 128, MTOT / 128, 1);
    gemm_mma<<<gq, t, SHM>>>(X, W,        bq, Q,  DIM, DIM, DIM, DIM, 0, 0, 0, 1.0f, 0, 1);
    gemm_mma<<<gq, t, SHM>>>(X, W + DD,   bk, Kb, DIM, DIM, DIM, DIM, 0, 0, 0, 1.0f, 0, 1);
    gemm_mma<<<gq, t, SHM>>>(X, W + 2*DD, bv, V,  DIM, DIM, DIM, DIM, 0, 0, 0, 1.0f, 0, 1);

    // VT[b][d][s] = V[b][s][d]
    transpose_sd<<<dim3(SEQ/32, DIM/32, BATCH), dim3(32, 8)>>>(V, VT);

    // scores = Q @ K^T * (1/32), lower-triangle blocks only (no rounding; softmax rounds)
    dim3 gs(SEQ / 128, SEQ / 128, BATCH);
    gemm_mma<<<gs, t, SHM>>>(Q, Kb, nullptr, P, DIM, DIM, DIM, SEQ,
                             SD, SD, SS, 0.03125f, 1, 0);

    // causal softmax in place (single pass, rounds P to tf32)
    softmax_causal<<<MTOT, 256>>>(P);

    // out = P @ V  (= P @ VT^T as NT), K truncated at causal boundary
    dim3 go(DIM / 128, SEQ / 128, BATCH);
    gemm_mma<<<go, t, SHM>>>(P, VT, nullptr, out, SEQ, SEQ, SEQ, DIM,
                             SS, SD, SD, 1.0f, 2, 0);
}